// round 5
// baseline (speedup 1.0000x reference)
#include <cuda_runtime.h>

#define NNODES 4096
#define MASK_WORDS 128   // 4096/32
#define NGRAPH 64

// ---------------- scratch (no allocations allowed) ----------------
__device__ unsigned g_mask[NNODES * MASK_WORDS];  // 2 MB bitmask of adj>0
__device__ float    g_f[NNODES * 64];             // per-layer head features [N][64] (head-major cols)
__device__ float    g_s[4 * NNODES];              // s1h0, s1h1, s2h0, s2h1
__device__ float    g_h[NNODES * 192];            // concat(x1,x2,x3)

// ---------------- K0: adjacency -> bitmask (float4 loads, DRAM-bound) ----------------
// Each lane loads 4 consecutive floats -> 4-bit nibble. A 32-bit mask word is
// built from 8 lanes' nibbles via 4 ballots (one per nibble bit).
__global__ void build_mask(const float* __restrict__ adj) {
    int row  = blockIdx.x;
    int warp = threadIdx.x >> 5, lane = threadIdx.x & 31;
    const float4* arow = reinterpret_cast<const float4*>(adj + (size_t)row * NNODES);
    // one warp covers 32 lanes * 4 floats = 128 floats = 4 mask words per iter
    for (int g = warp; g < 32; g += 4) {          // 32 groups of 128 floats
        float4 v = arow[g * 32 + lane];
        unsigned b0 = __ballot_sync(0xffffffffu, v.x > 0.0f);
        unsigned b1 = __ballot_sync(0xffffffffu, v.y > 0.0f);
        unsigned b2 = __ballot_sync(0xffffffffu, v.z > 0.0f);
        unsigned b3 = __ballot_sync(0xffffffffu, v.w > 0.0f);
        // lanes 0..3 each assemble one of the 4 mask words from 8-lane slices
        if (lane < 4) {
            int sh = lane * 8;
            unsigned n0 = (b0 >> sh) & 0xffu;
            unsigned n1 = (b1 >> sh) & 0xffu;
            unsigned n2 = (b2 >> sh) & 0xffu;
            unsigned n3 = (b3 >> sh) & 0xffu;
            // interleave: element e (0..31) of word = float index lane8*4+comp
            unsigned w = 0;
            #pragma unroll
            for (int i = 0; i < 8; i++) {
                w |= ((n0 >> i) & 1u) << (i * 4 + 0);
                w |= ((n1 >> i) & 1u) << (i * 4 + 1);
                w |= ((n2 >> i) & 1u) << (i * 4 + 2);
                w |= ((n3 >> i) & 1u) << (i * 4 + 3);
            }
            g_mask[row * MASK_WORDS + g * 4 + lane] = w;
        }
    }
}

// ---------------- K1: f = X @ Wcat + bcat  ([N,K] x [K,64]) ----------------
// W layout: [2][K][32] (head, k, feat). Output g_f[row][head*32+feat].
__global__ void gemm_f(const float* __restrict__ Xext, int use_h, int hcol,
                       int ldx, int K,
                       const float* __restrict__ W, const float* __restrict__ b) {
    __shared__ float As[32][33];
    __shared__ float Bs[32][64];
    const float* X = use_h ? (g_h + hcol) : Xext;
    int t = threadIdx.x;             // 256 threads
    int row0 = blockIdx.x * 32;
    int tx = t & 15, ty = t >> 4;    // tx: 16 col-groups of 4, ty: 16 row-groups of 2
    float acc[2][4] = {};
    for (int k0 = 0; k0 < K; k0 += 32) {
        #pragma unroll
        for (int i = 0; i < 4; i++) {
            int idx = t + i * 256;
            int r = idx >> 5, c = idx & 31;
            As[r][c] = X[(size_t)(row0 + r) * ldx + (k0 + c)];
        }
        #pragma unroll
        for (int i = 0; i < 8; i++) {
            int idx = t + i * 256;
            int kk = idx >> 6, n = idx & 63;
            int head = n >> 5, feat = n & 31;
            Bs[kk][n] = W[(size_t)(head * K + k0 + kk) * 32 + feat];
        }
        __syncthreads();
        #pragma unroll
        for (int kk = 0; kk < 32; kk++) {
            float a0 = As[ty * 2 + 0][kk];
            float a1 = As[ty * 2 + 1][kk];
            float4 bv = *reinterpret_cast<const float4*>(&Bs[kk][tx << 2]);
            acc[0][0] += a0 * bv.x; acc[0][1] += a0 * bv.y;
            acc[0][2] += a0 * bv.z; acc[0][3] += a0 * bv.w;
            acc[1][0] += a1 * bv.x; acc[1][1] += a1 * bv.y;
            acc[1][2] += a1 * bv.z; acc[1][3] += a1 * bv.w;
        }
        __syncthreads();
    }
    #pragma unroll
    for (int rr = 0; rr < 2; rr++) {
        #pragma unroll
        for (int j = 0; j < 4; j++) {
            int n = (tx << 2) + j;
            g_f[(size_t)(row0 + ty * 2 + rr) * 64 + n] = acc[rr][j] + b[n];
        }
    }
}

// ---------------- K2: attention scores s1, s2 per head ----------------
__global__ void compute_s(const float* __restrict__ a1w, const float* __restrict__ a1b,
                          const float* __restrict__ a2w, const float* __restrict__ a2b) {
    int row = blockIdx.x * blockDim.x + threadIdx.x;
    const float* fr = &g_f[(size_t)row * 64];
    float s10 = a1b[0], s11 = a1b[1], s20 = a2b[0], s21 = a2b[1];
    #pragma unroll
    for (int i = 0; i < 32; i++) {
        float f0 = fr[i], f1 = fr[32 + i];
        s10 += f0 * a1w[i];
        s11 += f1 * a1w[32 + i];
        s20 += f0 * a2w[i];
        s21 += f1 * a2w[32 + i];
    }
    g_s[row]              = s10;
    g_s[NNODES + row]     = s11;
    g_s[2 * NNODES + row] = s20;
    g_s[3 * NNODES + row] = s21;
}

// ---------------- K3: sparse masked softmax attention + relu, both heads ----------------
__global__ void __launch_bounds__(128) attn_kernel(int hoff) {
    __shared__ unsigned short s_idx[NNODES];  // 8 KB
    __shared__ float s_w0[NNODES];            // 16 KB (logits -> weights, head 0)
    __shared__ float s_w1[NNODES];            // 16 KB (head 1)
    __shared__ int   s_cnt;
    __shared__ float s_red[16];
    __shared__ float s_part[64];

    int row = blockIdx.x;
    int tid = threadIdx.x;
    int lane = tid & 31, wp = tid >> 5;
    if (tid == 0) s_cnt = 0;
    __syncthreads();

    // Phase A: gather set-bit neighbor indices
    const unsigned* mrow = &g_mask[row * MASK_WORDS];
    for (int w = tid; w < MASK_WORDS; w += 128) {
        unsigned m = mrow[w];
        while (m) {
            int bpos = __ffs(m) - 1;
            m &= m - 1;
            int pos = atomicAdd(&s_cnt, 1);
            s_idx[pos] = (unsigned short)(w * 32 + bpos);
        }
    }
    __syncthreads();
    int cnt = s_cnt;

    float s1_0 = g_s[row], s1_1 = g_s[NNODES + row];

    // Phase B: logits (leaky relu) + max
    float m0 = -1e30f, m1 = -1e30f;
    for (int t = tid; t < cnt; t += 128) {
        int j = s_idx[t];
        float e0 = s1_0 + g_s[2 * NNODES + j];
        float e1 = s1_1 + g_s[3 * NNODES + j];
        e0 = e0 > 0.f ? e0 : 0.01f * e0;
        e1 = e1 > 0.f ? e1 : 0.01f * e1;
        s_w0[t] = e0; s_w1[t] = e1;
        m0 = fmaxf(m0, e0); m1 = fmaxf(m1, e1);
    }
    #pragma unroll
    for (int o = 16; o; o >>= 1) {
        m0 = fmaxf(m0, __shfl_xor_sync(0xffffffffu, m0, o));
        m1 = fmaxf(m1, __shfl_xor_sync(0xffffffffu, m1, o));
    }
    if (lane == 0) { s_red[wp] = m0; s_red[4 + wp] = m1; }
    __syncthreads();
    m0 = fmaxf(fmaxf(s_red[0], s_red[1]), fmaxf(s_red[2], s_red[3]));
    m1 = fmaxf(fmaxf(s_red[4], s_red[5]), fmaxf(s_red[6], s_red[7]));

    // Phase C: exp + sum
    float sum0 = 0.f, sum1 = 0.f;
    for (int t = tid; t < cnt; t += 128) {
        float w0 = __expf(s_w0[t] - m0);
        float w1 = __expf(s_w1[t] - m1);
        s_w0[t] = w0; s_w1[t] = w1;
        sum0 += w0; sum1 += w1;
    }
    #pragma unroll
    for (int o = 16; o; o >>= 1) {
        sum0 += __shfl_xor_sync(0xffffffffu, sum0, o);
        sum1 += __shfl_xor_sync(0xffffffffu, sum1, o);
    }
    if (lane == 0) { s_red[8 + wp] = sum0; s_red[12 + wp] = sum1; }
    __syncthreads();
    float inv0 = 1.f / (s_red[8] + s_red[9] + s_red[10] + s_red[11]);
    float inv1 = 1.f / (s_red[12] + s_red[13] + s_red[14] + s_red[15]);

    // Phase D: out[k] = relu( (sum_j w_j * f[j][k]) / sum )
    // threads 0..63 handle even t, 64..127 odd t; feature k = tid & 63
    int k = tid & 63;
    const float* wptr = (k >> 5) ? s_w1 : s_w0;
    float acc = 0.f;
    #pragma unroll 4
    for (int t = (tid >> 6); t < cnt; t += 2) {
        acc += wptr[t] * g_f[(size_t)s_idx[t] * 64 + k];
    }
    if (tid >= 64) s_part[k] = acc;
    __syncthreads();
    if (tid < 64) {
        acc += s_part[k];
        float inv = (k >> 5) ? inv1 : inv0;
        float o = acc * inv;
        g_h[(size_t)row * 192 + hoff + k] = o > 0.f ? o : 0.f;
    }
}

// ---------------- K4: segment-mean pool + classifier + softmax ----------------
__global__ void final_kernel(const int* __restrict__ batch,
                             const float* __restrict__ Wf,
                             const float* __restrict__ bf,
                             float* __restrict__ out) {
    __shared__ float s_pool[192];
    __shared__ float s_log[10];
    int g = blockIdx.x;
    int tid = threadIdx.x;  // 192

    // lower_bound on sorted batch
    int lo = 0, hi = NNODES;
    while (lo < hi) { int mid = (lo + hi) >> 1; if (batch[mid] < g) lo = mid + 1; else hi = mid; }
    int start = lo;
    lo = start; hi = NNODES;
    while (lo < hi) { int mid = (lo + hi) >> 1; if (batch[mid] < g + 1) lo = mid + 1; else hi = mid; }
    int end = lo;
    int cnt = end - start;

    float sum = 0.f;
    for (int r = start; r < end; r++) sum += g_h[(size_t)r * 192 + tid];
    s_pool[tid] = sum / (float)(cnt > 0 ? cnt : 1);
    __syncthreads();

    if (tid < 10) {
        float l = bf[tid];
        for (int c = 0; c < 192; c++) l += s_pool[c] * Wf[c * 10 + tid];
        s_log[tid] = l;
    }
    __syncthreads();
    if (tid == 0) {
        float m = -1e30f;
        for (int o = 0; o < 10; o++) m = fmaxf(m, s_log[o]);
        float e[10], s = 0.f;
        for (int o = 0; o < 10; o++) { e[o] = __expf(s_log[o] - m); s += e[o]; }
        float inv = 1.f / s;
        for (int o = 0; o < 10; o++) out[g * 10 + o] = e[o] * inv;
    }
}

// ---------------- launch ----------------
extern "C" void kernel_launch(void* const* d_in, const int* in_sizes, int n_in,
                              void* d_out, int out_size) {
    const float* x   = (const float*)d_in[0];
    const float* adj = (const float*)d_in[1];
    const int* batch = (const int*)d_in[2];
    const float* W[3]   = {(const float*)d_in[3],  (const float*)d_in[9],  (const float*)d_in[15]};
    const float* b[3]   = {(const float*)d_in[4],  (const float*)d_in[10], (const float*)d_in[16]};
    const float* a1w[3] = {(const float*)d_in[5],  (const float*)d_in[11], (const float*)d_in[17]};
    const float* a1b[3] = {(const float*)d_in[6],  (const float*)d_in[12], (const float*)d_in[18]};
    const float* a2w[3] = {(const float*)d_in[7],  (const float*)d_in[13], (const float*)d_in[19]};
    const float* a2b[3] = {(const float*)d_in[8],  (const float*)d_in[14], (const float*)d_in[20]};
    const float* Wf = (const float*)d_in[21];
    const float* bf = (const float*)d_in[22];
    float* out = (float*)d_out;

    build_mask<<<NNODES, 128>>>(adj);

    for (int L = 0; L < 3; L++) {
        int K    = (L == 0) ? 512 : 64;
        int useh = (L == 0) ? 0 : 1;
        int hcol = (L == 0) ? 0 : (L - 1) * 64;
        int ldx  = (L == 0) ? 512 : 192;
        gemm_f<<<NNODES / 32, 256>>>(x, useh, hcol, ldx, K, W[L], b[L]);
        compute_s<<<NNODES / 256, 256>>>(a1w[L], a1b[L], a2w[L], a2b[L]);
        attn_kernel<<<NNODES, 128>>>(L * 64);
    }

    final_kernel<<<NGRAPH, 192>>>(batch, Wf, bf, out);
}

// round 6
// speedup vs baseline: 1.7940x; 1.7940x over previous
#include <cuda_runtime.h>

#define NNODES 4096
#define MASK_WORDS 128   // 4096/32
#define NGRAPH 64
#define MAXNBR 320       // binomial(4096,0.02): mean 82, sigma 9 -> 320 is ~26 sigma (clamped anyway)

// ---------------- scratch (no allocations allowed) ----------------
__device__ unsigned g_mask[NNODES * MASK_WORDS];  // 2 MB bitmask of adj>0
__device__ float    g_f[NNODES * 64];             // per-layer head features [N][64]
__device__ float    g_s[4 * NNODES];              // s1h0, s1h1, s2h0, s2h1
__device__ float    g_h[NNODES * 192];            // concat(x1,x2,x3)

// ---------------- K0: adjacency -> bitmask (float4 loads, DRAM-bound) ----------------
__global__ void build_mask(const float* __restrict__ adj) {
    int row  = blockIdx.x;
    int warp = threadIdx.x >> 5, lane = threadIdx.x & 31;
    const float4* arow = reinterpret_cast<const float4*>(adj + (size_t)row * NNODES);
    for (int g = warp; g < 32; g += 4) {          // 32 groups of 128 floats
        float4 v = arow[g * 32 + lane];
        unsigned b0 = __ballot_sync(0xffffffffu, v.x > 0.0f);
        unsigned b1 = __ballot_sync(0xffffffffu, v.y > 0.0f);
        unsigned b2 = __ballot_sync(0xffffffffu, v.z > 0.0f);
        unsigned b3 = __ballot_sync(0xffffffffu, v.w > 0.0f);
        if (lane < 4) {
            int sh = lane * 8;
            unsigned n0 = (b0 >> sh) & 0xffu;
            unsigned n1 = (b1 >> sh) & 0xffu;
            unsigned n2 = (b2 >> sh) & 0xffu;
            unsigned n3 = (b3 >> sh) & 0xffu;
            unsigned w = 0;
            #pragma unroll
            for (int i = 0; i < 8; i++) {
                w |= ((n0 >> i) & 1u) << (i * 4 + 0);
                w |= ((n1 >> i) & 1u) << (i * 4 + 1);
                w |= ((n2 >> i) & 1u) << (i * 4 + 2);
                w |= ((n3 >> i) & 1u) << (i * 4 + 3);
            }
            g_mask[row * MASK_WORDS + g * 4 + lane] = w;
        }
    }
}

// ---------------- K1: f = X @ Wcat + bcat, fused s1/s2 epilogue ----------------
// W layout: [2][K][32] (head, k, feat). Output g_f[row][head*32+feat].
// Epilogue: s1[row,head] = f . a1w[head] + a1b[head] (likewise s2), via 8-lane shfl reduce.
__global__ void gemm_f(const float* __restrict__ Xext, int use_h, int hcol,
                       int ldx, int K,
                       const float* __restrict__ W, const float* __restrict__ b,
                       const float* __restrict__ a1w, const float* __restrict__ a1b,
                       const float* __restrict__ a2w, const float* __restrict__ a2b) {
    __shared__ float As[32][33];
    __shared__ float Bs[32][64];
    const float* X = use_h ? (g_h + hcol) : Xext;
    int t = threadIdx.x;             // 256 threads
    int row0 = blockIdx.x * 32;
    int tx = t & 15, ty = t >> 4;    // tx: 16 col-groups of 4, ty: 16 row-groups of 2
    float acc[2][4] = {};
    for (int k0 = 0; k0 < K; k0 += 32) {
        #pragma unroll
        for (int i = 0; i < 4; i++) {
            int idx = t + i * 256;
            int r = idx >> 5, c = idx & 31;
            As[r][c] = X[(size_t)(row0 + r) * ldx + (k0 + c)];
        }
        #pragma unroll
        for (int i = 0; i < 8; i++) {
            int idx = t + i * 256;
            int kk = idx >> 6, n = idx & 63;
            int head = n >> 5, feat = n & 31;
            Bs[kk][n] = W[(size_t)(head * K + k0 + kk) * 32 + feat];
        }
        __syncthreads();
        #pragma unroll
        for (int kk = 0; kk < 32; kk++) {
            float a0 = As[ty * 2 + 0][kk];
            float a1 = As[ty * 2 + 1][kk];
            float4 bv = *reinterpret_cast<const float4*>(&Bs[kk][tx << 2]);
            acc[0][0] += a0 * bv.x; acc[0][1] += a0 * bv.y;
            acc[0][2] += a0 * bv.z; acc[0][3] += a0 * bv.w;
            acc[1][0] += a1 * bv.x; acc[1][1] += a1 * bv.y;
            acc[1][2] += a1 * bv.z; acc[1][3] += a1 * bv.w;
        }
        __syncthreads();
    }
    // write f + accumulate partial attention scores
    float p1[2] = {0.f, 0.f}, p2[2] = {0.f, 0.f};
    #pragma unroll
    for (int rr = 0; rr < 2; rr++) {
        #pragma unroll
        for (int j = 0; j < 4; j++) {
            int n = (tx << 2) + j;          // col; head = n>>5 constant per thread
            float v = acc[rr][j] + b[n];
            g_f[(size_t)(row0 + ty * 2 + rr) * 64 + n] = v;
            p1[rr] += v * a1w[n];           // a1w layout [2][32] == flat [n]
            p2[rr] += v * a2w[n];
        }
    }
    // reduce over the 8 lanes sharing (row pair, head): tx 0-7 = head0, 8-15 = head1,
    // lane = (ty&1)*16 + tx, so groups are 8-lane aligned -> xor 1,2,4 stays inside.
    #pragma unroll
    for (int o = 1; o < 8; o <<= 1) {
        p1[0] += __shfl_xor_sync(0xffffffffu, p1[0], o);
        p1[1] += __shfl_xor_sync(0xffffffffu, p1[1], o);
        p2[0] += __shfl_xor_sync(0xffffffffu, p2[0], o);
        p2[1] += __shfl_xor_sync(0xffffffffu, p2[1], o);
    }
    if ((tx & 7) == 0) {
        int head = tx >> 3;
        int r0 = row0 + ty * 2;
        g_s[head * NNODES + r0]           = p1[0] + a1b[head];
        g_s[head * NNODES + r0 + 1]       = p1[1] + a1b[head];
        g_s[(2 + head) * NNODES + r0]     = p2[0] + a2b[head];
        g_s[(2 + head) * NNODES + r0 + 1] = p2[1] + a2b[head];
    }
}

// ---------------- K2: warp-per-row sparse masked softmax attention + relu ----------------
// 8 warps per CTA, one row each. No block syncs; deterministic scan-based gather.
__global__ void __launch_bounds__(256) attn_kernel(int hoff) {
    __shared__ unsigned short s_idx[8][MAXNBR];  // 5 KB
    __shared__ float s_e0[8][MAXNBR];            // 10 KB
    __shared__ float s_e1[8][MAXNBR];            // 10 KB

    int wp = threadIdx.x >> 5, lane = threadIdx.x & 31;
    int row = blockIdx.x * 8 + wp;

    // Phase A: gather set-bit neighbor indices (warp scan, deterministic order)
    const unsigned* mrow = &g_mask[row * MASK_WORDS];
    unsigned m[4];
    int c = 0;
    #pragma unroll
    for (int i = 0; i < 4; i++) { m[i] = mrow[lane * 4 + i]; c += __popc(m[i]); }
    int inc = c;
    #pragma unroll
    for (int o = 1; o < 32; o <<= 1) {
        int n = __shfl_up_sync(0xffffffffu, inc, o);
        if (lane >= o) inc += n;
    }
    int cnt = __shfl_sync(0xffffffffu, inc, 31);
    int pos = inc - c;
    #pragma unroll
    for (int i = 0; i < 4; i++) {
        unsigned mm = m[i];
        int base = (lane * 4 + i) * 32;
        while (mm) {
            int bp = __ffs(mm) - 1; mm &= mm - 1;
            if (pos < MAXNBR) s_idx[wp][pos] = (unsigned short)(base + bp);
            pos++;
        }
    }
    if (cnt > MAXNBR) cnt = MAXNBR;
    __syncwarp();

    // Phase B: logits (leaky relu) + warp max
    float s1_0 = g_s[row], s1_1 = g_s[NNODES + row];
    float mx0 = -1e30f, mx1 = -1e30f;
    for (int t = lane; t < cnt; t += 32) {
        int j = s_idx[wp][t];
        float e0 = s1_0 + g_s[2 * NNODES + j];
        float e1 = s1_1 + g_s[3 * NNODES + j];
        e0 = e0 > 0.f ? e0 : 0.01f * e0;
        e1 = e1 > 0.f ? e1 : 0.01f * e1;
        s_e0[wp][t] = e0; s_e1[wp][t] = e1;
        mx0 = fmaxf(mx0, e0); mx1 = fmaxf(mx1, e1);
    }
    #pragma unroll
    for (int o = 16; o; o >>= 1) {
        mx0 = fmaxf(mx0, __shfl_xor_sync(0xffffffffu, mx0, o));
        mx1 = fmaxf(mx1, __shfl_xor_sync(0xffffffffu, mx1, o));
    }
    __syncwarp();

    // Phase C: exp + warp sum
    float sum0 = 0.f, sum1 = 0.f;
    for (int t = lane; t < cnt; t += 32) {
        float w0 = __expf(s_e0[wp][t] - mx0);
        float w1 = __expf(s_e1[wp][t] - mx1);
        s_e0[wp][t] = w0; s_e1[wp][t] = w1;
        sum0 += w0; sum1 += w1;
    }
    #pragma unroll
    for (int o = 16; o; o >>= 1) {
        sum0 += __shfl_xor_sync(0xffffffffu, sum0, o);
        sum1 += __shfl_xor_sync(0xffffffffu, sum1, o);
    }
    float inv0 = 1.f / sum0, inv1 = 1.f / sum1;
    __syncwarp();

    // Phase D: lane k accumulates features k (head0) and 32+k (head1)
    float acc0 = 0.f, acc1 = 0.f;
    #pragma unroll 4
    for (int t = 0; t < cnt; t++) {
        float w0 = s_e0[wp][t];
        float w1 = s_e1[wp][t];
        const float* fj = &g_f[(size_t)s_idx[wp][t] * 64];
        acc0 += w0 * fj[lane];
        acc1 += w1 * fj[32 + lane];
    }
    float* hr = &g_h[(size_t)row * 192 + hoff];
    float o0 = acc0 * inv0, o1 = acc1 * inv1;
    hr[lane]      = o0 > 0.f ? o0 : 0.f;
    hr[32 + lane] = o1 > 0.f ? o1 : 0.f;
}

// ---------------- K3: segment-mean pool + classifier + softmax ----------------
__global__ void final_kernel(const int* __restrict__ batch,
                             const float* __restrict__ Wf,
                             const float* __restrict__ bf,
                             float* __restrict__ out) {
    __shared__ float s_pool[192];
    __shared__ float s_log[10];
    int g = blockIdx.x;
    int tid = threadIdx.x;  // 192

    int lo = 0, hi = NNODES;
    while (lo < hi) { int mid = (lo + hi) >> 1; if (batch[mid] < g) lo = mid + 1; else hi = mid; }
    int start = lo;
    lo = start; hi = NNODES;
    while (lo < hi) { int mid = (lo + hi) >> 1; if (batch[mid] < g + 1) lo = mid + 1; else hi = mid; }
    int end = lo;
    int cnt = end - start;

    float sum = 0.f;
    for (int r = start; r < end; r++) sum += g_h[(size_t)r * 192 + tid];
    s_pool[tid] = sum / (float)(cnt > 0 ? cnt : 1);
    __syncthreads();

    if (tid < 10) {
        float l = bf[tid];
        for (int c = 0; c < 192; c++) l += s_pool[c] * Wf[c * 10 + tid];
        s_log[tid] = l;
    }
    __syncthreads();
    if (tid == 0) {
        float m = -1e30f;
        for (int o = 0; o < 10; o++) m = fmaxf(m, s_log[o]);
        float e[10], s = 0.f;
        for (int o = 0; o < 10; o++) { e[o] = __expf(s_log[o] - m); s += e[o]; }
        float inv = 1.f / s;
        for (int o = 0; o < 10; o++) out[g * 10 + o] = e[o] * inv;
    }
}

// ---------------- launch ----------------
extern "C" void kernel_launch(void* const* d_in, const int* in_sizes, int n_in,
                              void* d_out, int out_size) {
    const float* x   = (const float*)d_in[0];
    const float* adj = (const float*)d_in[1];
    const int* batch = (const int*)d_in[2];
    const float* W[3]   = {(const float*)d_in[3],  (const float*)d_in[9],  (const float*)d_in[15]};
    const float* b[3]   = {(const float*)d_in[4],  (const float*)d_in[10], (const float*)d_in[16]};
    const float* a1w[3] = {(const float*)d_in[5],  (const float*)d_in[11], (const float*)d_in[17]};
    const float* a1b[3] = {(const float*)d_in[6],  (const float*)d_in[12], (const float*)d_in[18]};
    const float* a2w[3] = {(const float*)d_in[7],  (const float*)d_in[13], (const float*)d_in[19]};
    const float* a2b[3] = {(const float*)d_in[8],  (const float*)d_in[14], (const float*)d_in[20]};
    const float* Wf = (const float*)d_in[21];
    const float* bf = (const float*)d_in[22];
    float* out = (float*)d_out;

    build_mask<<<NNODES, 128>>>(adj);

    for (int L = 0; L < 3; L++) {
        int K    = (L == 0) ? 512 : 64;
        int useh = (L == 0) ? 0 : 1;
        int hcol = (L == 0) ? 0 : (L - 1) * 64;
        int ldx  = (L == 0) ? 512 : 192;
        gemm_f<<<NNODES / 32, 256>>>(x, useh, hcol, ldx, K, W[L], b[L],
                                     a1w[L], a1b[L], a2w[L], a2b[L]);
        attn_kernel<<<NNODES / 8, 256>>>(L * 64);
    }

    final_kernel<<<NGRAPH, 192>>>(batch, Wf, bf, out);
}

// round 10
// speedup vs baseline: 1.9089x; 1.0640x over previous
#include <cuda_runtime.h>

#define NNODES 4096
#define MASK_WORDS 128   // 4096/32
#define NGRAPH 64
#define MAXNBR 320       // binomial(4096,0.02): mean 82, sigma 9 (clamped defensively)

// ---------------- scratch (no allocations allowed) ----------------
__device__ unsigned g_mask[NNODES * MASK_WORDS];  // 2 MB bitmask of adj>0
__device__ float    g_f[NNODES * 64];             // per-layer head features [N][64]
__device__ float    g_s[4 * NNODES];              // s1h0, s1h1, s2h0, s2h1
__device__ float    g_h[NNODES * 192];            // concat(x1,x2,x3)

// ---------------- K1: f = X @ Wcat + bcat, fused s1/s2 epilogue ----------------
// 16-row x 64-col tiles, 128 threads, register-prefetch pipeline. grid = 256.
// W layout: [2][K][32] (head, k, feat). Output g_f[row][head*32+feat].
__global__ void __launch_bounds__(128) gemm_f(
        const float* __restrict__ Xext, int use_h, int hcol,
        int ldx, int K,
        const float* __restrict__ W, const float* __restrict__ b,
        const float* __restrict__ a1w, const float* __restrict__ a1b,
        const float* __restrict__ a2w, const float* __restrict__ a2b) {
    __shared__ float As[16][33];
    __shared__ float Bs[32][64];
    const float* X = use_h ? (g_h + hcol) : Xext;
    int t = threadIdx.x;             // 128 threads
    int row0 = blockIdx.x * 16;
    int tx = t & 15, ty = t >> 4;    // tx: 16 col-groups of 4, ty: 8 row-pairs

    float acc[2][4] = {};
    float aR[4];
    float4 bR[4];

    const int KT = K >> 5;

    // prefetch helpers (mapping is fixed per thread)
    // A: idx = t + i*128 -> r = idx>>5, c = idx&31   (16x32 = 512 elems)
    // B: idx = t + i*128 -> kk = idx>>4, f4g = idx&15; head=f4g>>3, f4=f4g&7
    #pragma unroll
    for (int i = 0; i < 4; i++) {
        int idx = t + i * 128;
        aR[i] = X[(size_t)(row0 + (idx >> 5)) * ldx + (idx & 31)];
        int kk = idx >> 4, f4g = idx & 15;
        int head = f4g >> 3, f4 = f4g & 7;
        bR[i] = *reinterpret_cast<const float4*>(&W[(size_t)(head * K + kk) * 32 + f4 * 4]);
    }

    for (int kt = 0; kt < KT; kt++) {
        __syncthreads();  // previous compute done reading smem
        #pragma unroll
        for (int i = 0; i < 4; i++) {
            int idx = t + i * 128;
            As[idx >> 5][idx & 31] = aR[i];
            int kk = idx >> 4, f4g = idx & 15;
            reinterpret_cast<float4*>(&Bs[kk][0])[f4g] = bR[i];
        }
        __syncthreads();
        if (kt + 1 < KT) {
            int k0 = (kt + 1) << 5;
            #pragma unroll
            for (int i = 0; i < 4; i++) {
                int idx = t + i * 128;
                aR[i] = X[(size_t)(row0 + (idx >> 5)) * ldx + (k0 + (idx & 31))];
                int kk = idx >> 4, f4g = idx & 15;
                int head = f4g >> 3, f4 = f4g & 7;
                bR[i] = *reinterpret_cast<const float4*>(&W[(size_t)(head * K + k0 + kk) * 32 + f4 * 4]);
            }
        }
        #pragma unroll
        for (int kk = 0; kk < 32; kk++) {
            float a0 = As[ty * 2 + 0][kk];
            float a1 = As[ty * 2 + 1][kk];
            float4 bv = reinterpret_cast<const float4*>(&Bs[kk][0])[tx];
            acc[0][0] += a0 * bv.x; acc[0][1] += a0 * bv.y;
            acc[0][2] += a0 * bv.z; acc[0][3] += a0 * bv.w;
            acc[1][0] += a1 * bv.x; acc[1][1] += a1 * bv.y;
            acc[1][2] += a1 * bv.z; acc[1][3] += a1 * bv.w;
        }
    }

    // epilogue: write f + fused attention-score partials
    float p1[2] = {0.f, 0.f}, p2[2] = {0.f, 0.f};
    #pragma unroll
    for (int rr = 0; rr < 2; rr++) {
        #pragma unroll
        for (int j = 0; j < 4; j++) {
            int n = (tx << 2) + j;          // col; head = n>>5 constant per thread
            float v = acc[rr][j] + b[n];
            g_f[(size_t)(row0 + ty * 2 + rr) * 64 + n] = v;
            p1[rr] += v * a1w[n];
            p2[rr] += v * a2w[n];
        }
    }
    // 8-lane groups share (row-pair, head): lane = ((ty&1)<<4)|tx
    #pragma unroll
    for (int o = 1; o < 8; o <<= 1) {
        p1[0] += __shfl_xor_sync(0xffffffffu, p1[0], o);
        p1[1] += __shfl_xor_sync(0xffffffffu, p1[1], o);
        p2[0] += __shfl_xor_sync(0xffffffffu, p2[0], o);
        p2[1] += __shfl_xor_sync(0xffffffffu, p2[1], o);
    }
    if ((tx & 7) == 0) {
        int head = tx >> 3;
        int r0 = row0 + ty * 2;
        g_s[head * NNODES + r0]           = p1[0] + a1b[head];
        g_s[head * NNODES + r0 + 1]       = p1[1] + a1b[head];
        g_s[(2 + head) * NNODES + r0]     = p2[0] + a2b[head];
        g_s[(2 + head) * NNODES + r0 + 1] = p2[1] + a2b[head];
    }
}

// ---------------- shared attention body (phases B-D), warp-per-row ----------------
__device__ __forceinline__ void attn_body(int wp, int lane, int row, int cnt,
                                          unsigned short (*s_idx)[MAXNBR],
                                          float (*s_e0)[MAXNBR],
                                          float (*s_e1)[MAXNBR],
                                          int hoff) {
    // Phase B: logits (leaky relu) + warp max
    float s1_0 = g_s[row], s1_1 = g_s[NNODES + row];
    float mx0 = -1e30f, mx1 = -1e30f;
    for (int t = lane; t < cnt; t += 32) {
        int j = s_idx[wp][t];
        float e0 = s1_0 + g_s[2 * NNODES + j];
        float e1 = s1_1 + g_s[3 * NNODES + j];
        e0 = e0 > 0.f ? e0 : 0.01f * e0;
        e1 = e1 > 0.f ? e1 : 0.01f * e1;
        s_e0[wp][t] = e0; s_e1[wp][t] = e1;
        mx0 = fmaxf(mx0, e0); mx1 = fmaxf(mx1, e1);
    }
    #pragma unroll
    for (int o = 16; o; o >>= 1) {
        mx0 = fmaxf(mx0, __shfl_xor_sync(0xffffffffu, mx0, o));
        mx1 = fmaxf(mx1, __shfl_xor_sync(0xffffffffu, mx1, o));
    }
    __syncwarp();

    // Phase C: exp + warp sum
    float sum0 = 0.f, sum1 = 0.f;
    for (int t = lane; t < cnt; t += 32) {
        float w0 = __expf(s_e0[wp][t] - mx0);
        float w1 = __expf(s_e1[wp][t] - mx1);
        s_e0[wp][t] = w0; s_e1[wp][t] = w1;
        sum0 += w0; sum1 += w1;
    }
    #pragma unroll
    for (int o = 16; o; o >>= 1) {
        sum0 += __shfl_xor_sync(0xffffffffu, sum0, o);
        sum1 += __shfl_xor_sync(0xffffffffu, sum1, o);
    }
    float inv0 = 1.f / sum0, inv1 = 1.f / sum1;
    __syncwarp();

    // Phase D: lane k accumulates features k (head0) and 32+k (head1)
    float acc0 = 0.f, acc1 = 0.f;
    #pragma unroll 4
    for (int t = 0; t < cnt; t++) {
        float w0 = s_e0[wp][t];
        float w1 = s_e1[wp][t];
        const float* fj = &g_f[(size_t)s_idx[wp][t] * 64];
        acc0 += w0 * fj[lane];
        acc1 += w1 * fj[32 + lane];
    }
    float* hr = &g_h[(size_t)row * 192 + hoff];
    float o0 = acc0 * inv0, o1 = acc1 * inv1;
    hr[lane]      = o0 > 0.f ? o0 : 0.f;
    hr[32 + lane] = o1 > 0.f ? o1 : 0.f;
}

// ---------------- K2a: layer-1 attention fused with mask build (reads adj) ----------------
__global__ void __launch_bounds__(256) attn_build(const float* __restrict__ adj) {
    __shared__ unsigned s_words[8][MASK_WORDS];  // 4 KB
    __shared__ unsigned short s_idx[8][MAXNBR];  // 5 KB
    __shared__ float s_e0[8][MAXNBR];            // 10 KB
    __shared__ float s_e1[8][MAXNBR];            // 10 KB

    int wp = threadIdx.x >> 5, lane = threadIdx.x & 31;
    int row = blockIdx.x * 8 + wp;

    // Phase A0: read adj row, ballot into mask words (also persisted for layers 2/3)
    const float4* arow = reinterpret_cast<const float4*>(adj + (size_t)row * NNODES);
    #pragma unroll 4
    for (int g = 0; g < 32; g++) {
        float4 v = arow[g * 32 + lane];
        unsigned b0 = __ballot_sync(0xffffffffu, v.x > 0.0f);
        unsigned b1 = __ballot_sync(0xffffffffu, v.y > 0.0f);
        unsigned b2 = __ballot_sync(0xffffffffu, v.z > 0.0f);
        unsigned b3 = __ballot_sync(0xffffffffu, v.w > 0.0f);
        if (lane < 4) {
            int sh = lane * 8;
            unsigned n0 = (b0 >> sh) & 0xffu;
            unsigned n1 = (b1 >> sh) & 0xffu;
            unsigned n2 = (b2 >> sh) & 0xffu;
            unsigned n3 = (b3 >> sh) & 0xffu;
            unsigned w = 0;
            #pragma unroll
            for (int i = 0; i < 8; i++) {
                w |= ((n0 >> i) & 1u) << (i * 4 + 0);
                w |= ((n1 >> i) & 1u) << (i * 4 + 1);
                w |= ((n2 >> i) & 1u) << (i * 4 + 2);
                w |= ((n3 >> i) & 1u) << (i * 4 + 3);
            }
            s_words[wp][g * 4 + lane] = w;
        }
    }
    __syncwarp();

    // Phase A1: scan + extract indices; persist mask
    unsigned m[4];
    int c = 0;
    #pragma unroll
    for (int i = 0; i < 4; i++) {
        m[i] = s_words[wp][lane * 4 + i];
        g_mask[row * MASK_WORDS + lane * 4 + i] = m[i];
        c += __popc(m[i]);
    }
    int inc = c;
    #pragma unroll
    for (int o = 1; o < 32; o <<= 1) {
        int n = __shfl_up_sync(0xffffffffu, inc, o);
        if (lane >= o) inc += n;
    }
    int cnt = __shfl_sync(0xffffffffu, inc, 31);
    int pos = inc - c;
    #pragma unroll
    for (int i = 0; i < 4; i++) {
        unsigned mm = m[i];
        int base = (lane * 4 + i) * 32;
        while (mm) {
            int bp = __ffs(mm) - 1; mm &= mm - 1;
            if (pos < MAXNBR) s_idx[wp][pos] = (unsigned short)(base + bp);
            pos++;
        }
    }
    if (cnt > MAXNBR) cnt = MAXNBR;
    __syncwarp();

    attn_body(wp, lane, row, cnt, s_idx, s_e0, s_e1, 0);
}

// ---------------- K2b: layers 2/3 attention (reads 2MB mask) ----------------
__global__ void __launch_bounds__(256) attn_kernel(int hoff) {
    __shared__ unsigned short s_idx[8][MAXNBR];
    __shared__ float s_e0[8][MAXNBR];
    __shared__ float s_e1[8][MAXNBR];

    int wp = threadIdx.x >> 5, lane = threadIdx.x & 31;
    int row = blockIdx.x * 8 + wp;

    const unsigned* mrow = &g_mask[row * MASK_WORDS];
    unsigned m[4];
    int c = 0;
    #pragma unroll
    for (int i = 0; i < 4; i++) { m[i] = mrow[lane * 4 + i]; c += __popc(m[i]); }
    int inc = c;
    #pragma unroll
    for (int o = 1; o < 32; o <<= 1) {
        int n = __shfl_up_sync(0xffffffffu, inc, o);
        if (lane >= o) inc += n;
    }
    int cnt = __shfl_sync(0xffffffffu, inc, 31);
    int pos = inc - c;
    #pragma unroll
    for (int i = 0; i < 4; i++) {
        unsigned mm = m[i];
        int base = (lane * 4 + i) * 32;
        while (mm) {
            int bp = __ffs(mm) - 1; mm &= mm - 1;
            if (pos < MAXNBR) s_idx[wp][pos] = (unsigned short)(base + bp);
            pos++;
        }
    }
    if (cnt > MAXNBR) cnt = MAXNBR;
    __syncwarp();

    attn_body(wp, lane, row, cnt, s_idx, s_e0, s_e1, hoff);
}

// ---------------- K3: segment-mean pool + classifier + softmax ----------------
__global__ void final_kernel(const int* __restrict__ batch,
                             const float* __restrict__ Wf,
                             const float* __restrict__ bf,
                             float* __restrict__ out) {
    __shared__ float s_pool[192];
    __shared__ float s_log[10];
    int g = blockIdx.x;
    int tid = threadIdx.x;  // 192

    int lo = 0, hi = NNODES;
    while (lo < hi) { int mid = (lo + hi) >> 1; if (batch[mid] < g) lo = mid + 1; else hi = mid; }
    int start = lo;
    lo = start; hi = NNODES;
    while (lo < hi) { int mid = (lo + hi) >> 1; if (batch[mid] < g + 1) lo = mid + 1; else hi = mid; }
    int end = lo;
    int cnt = end - start;

    float sum = 0.f;
    for (int r = start; r < end; r++) sum += g_h[(size_t)r * 192 + tid];
    s_pool[tid] = sum / (float)(cnt > 0 ? cnt : 1);
    __syncthreads();

    if (tid < 10) {
        float l = bf[tid];
        for (int c = 0; c < 192; c++) l += s_pool[c] * Wf[c * 10 + tid];
        s_log[tid] = l;
    }
    __syncthreads();
    if (tid == 0) {
        float m = -1e30f;
        for (int o = 0; o < 10; o++) m = fmaxf(m, s_log[o]);
        float e[10], s = 0.f;
        for (int o = 0; o < 10; o++) { e[o] = __expf(s_log[o] - m); s += e[o]; }
        float inv = 1.f / s;
        for (int o = 0; o < 10; o++) out[g * 10 + o] = e[o] * inv;
    }
}

// ---------------- launch ----------------
extern "C" void kernel_launch(void* const* d_in, const int* in_sizes, int n_in,
                              void* d_out, int out_size) {
    const float* x   = (const float*)d_in[0];
    const float* adj = (const float*)d_in[1];
    const int* batch = (const int*)d_in[2];
    const float* W[3]   = {(const float*)d_in[3],  (const float*)d_in[9],  (const float*)d_in[15]};
    const float* b[3]   = {(const float*)d_in[4],  (const float*)d_in[10], (const float*)d_in[16]};
    const float* a1w[3] = {(const float*)d_in[5],  (const float*)d_in[11], (const float*)d_in[17]};
    const float* a1b[3] = {(const float*)d_in[6],  (const float*)d_in[12], (const float*)d_in[18]};
    const float* a2w[3] = {(const float*)d_in[7],  (const float*)d_in[13], (const float*)d_in[19]};
    const float* a2b[3] = {(const float*)d_in[8],  (const float*)d_in[14], (const float*)d_in[20]};
    const float* Wf = (const float*)d_in[21];
    const float* bf = (const float*)d_in[22];
    float* out = (float*)d_out;

    for (int L = 0; L < 3; L++) {
        int K    = (L == 0) ? 512 : 64;
        int useh = (L == 0) ? 0 : 1;
        int hcol = (L == 0) ? 0 : (L - 1) * 64;
        int ldx  = (L == 0) ? 512 : 192;
        gemm_f<<<NNODES / 16, 128>>>(x, useh, hcol, ldx, K, W[L], b[L],
                                     a1w[L], a1b[L], a2w[L], a2b[L]);
        if (L == 0) attn_build<<<NNODES / 8, 256>>>(adj);
        else        attn_kernel<<<NNODES / 8, 256>>>(L * 64);
    }

    final_kernel<<<NGRAPH, 192>>>(batch, Wf, bf, out);
}